// round 2
// baseline (speedup 1.0000x reference)
#include <cuda_runtime.h>
#include <cuda_bf16.h>
#include <cstdint>

// Problem constants
#define BATCH 2048
#define FEAT  2048
#define NKERN 128
#define NDIM  16
#define NCOL  (NKERN * NDIM)   // 2048

// ---------------------------------------------------------------------------
// Scratch (no allocations allowed — __device__ globals)
// ---------------------------------------------------------------------------
__device__ __nv_bfloat16 g_xb[(size_t)BATCH * FEAT];   // 8 MB
__device__ __nv_bfloat16 g_wb[(size_t)FEAT * NCOL];    // 8 MB
__device__ float         g_M [(size_t)BATCH * NCOL];   // 16 MB

// ---------------------------------------------------------------------------
// Kernel 1: fp32 -> bf16 conversion for x and W
// ---------------------------------------------------------------------------
__global__ void cvt_kernel(const float* __restrict__ x,
                           const float* __restrict__ W) {
    int idx = blockIdx.x * blockDim.x + threadIdx.x;   // one float4 of each
    const float4 vx = reinterpret_cast<const float4*>(x)[idx];
    const float4 vw = reinterpret_cast<const float4*>(W)[idx];

    __nv_bfloat162* px = reinterpret_cast<__nv_bfloat162*>(g_xb);
    __nv_bfloat162* pw = reinterpret_cast<__nv_bfloat162*>(g_wb);
    px[2 * idx + 0] = __floats2bfloat162_rn(vx.x, vx.y);
    px[2 * idx + 1] = __floats2bfloat162_rn(vx.z, vx.w);
    pw[2 * idx + 0] = __floats2bfloat162_rn(vw.x, vw.y);
    pw[2 * idx + 1] = __floats2bfloat162_rn(vw.z, vw.w);
}

// ---------------------------------------------------------------------------
// Kernel 2: bf16 tensor-core GEMM, 2-stage cp.async pipeline.
// Tile: BM=128, BN=128, BK=32, 256 threads (8 warps), warp tile 32x64.
// ---------------------------------------------------------------------------
#define BM   128
#define BN   128
#define BKT  32
#define APAD 8     // As row stride 40 bf16 = 20 words -> conflict-free ldmatrix
#define BPAD 8     // Bs row stride 136 bf16 = 68 words -> conflict-free

__device__ __forceinline__ uint32_t smem_u32(const void* p) {
    uint32_t a;
    asm("{ .reg .u64 t; cvta.to.shared.u64 t, %1; cvt.u32.u64 %0, t; }"
        : "=r"(a) : "l"(p));
    return a;
}

__device__ __forceinline__ void cp_async16(uint32_t smem, const void* gmem) {
    asm volatile("cp.async.cg.shared.global [%0], [%1], 16;\n"
                 :: "r"(smem), "l"(gmem));
}
#define CP_COMMIT()  asm volatile("cp.async.commit_group;\n" ::: "memory")
#define CP_WAIT1()   asm volatile("cp.async.wait_group 1;\n" ::: "memory")

__global__ __launch_bounds__(256) void gemm_kernel() {
    __shared__ __nv_bfloat16 As[2][BM][BKT + APAD];   // 2 x 10240 B
    __shared__ __nv_bfloat16 Bs[2][BKT][BN + BPAD];   // 2 x  8704 B

    const int tid  = threadIdx.x;
    const int warp = tid >> 5;
    const int lane = tid & 31;
    const int wm   = (warp & 3) * 32;   // warp row offset in block tile
    const int wn   = (warp >> 2) * 64;  // warp col offset in block tile
    const int bm   = blockIdx.y * BM;
    const int bn   = blockIdx.x * BN;

    // Per-thread load coordinates (fixed across iterations)
    const int ar0 = tid >> 2;            // A rows for i=0 / i=1: ar0, ar0+64
    const int ac  = (tid & 3) * 8;
    const int br0 = tid >> 4;            // B rows: br0, br0+16
    const int bc  = (tid & 15) * 8;

    float acc[2][8][4];
#pragma unroll
    for (int mt = 0; mt < 2; mt++)
#pragma unroll
        for (int nt = 0; nt < 8; nt++)
#pragma unroll
            for (int q = 0; q < 4; q++) acc[mt][nt][q] = 0.0f;

    const uint32_t a_smem0 = smem_u32(&As[0][0][0]);
    const uint32_t b_smem0 = smem_u32(&Bs[0][0][0]);
    const uint32_t a_stage = (uint32_t)sizeof(As[0]);
    const uint32_t b_stage = (uint32_t)sizeof(Bs[0]);

    auto load_tiles = [&](int k0, int s) {
        const uint32_t abase = a_smem0 + s * a_stage;
        const uint32_t bbase = b_smem0 + s * b_stage;
        cp_async16(abase + (uint32_t)(ar0 * (BKT + APAD) + ac) * 2u,
                   &g_xb[(size_t)(bm + ar0) * FEAT + k0 + ac]);
        cp_async16(abase + (uint32_t)((ar0 + 64) * (BKT + APAD) + ac) * 2u,
                   &g_xb[(size_t)(bm + ar0 + 64) * FEAT + k0 + ac]);
        cp_async16(bbase + (uint32_t)(br0 * (BN + BPAD) + bc) * 2u,
                   &g_wb[(size_t)(k0 + br0) * NCOL + bn + bc]);
        cp_async16(bbase + (uint32_t)((br0 + 16) * (BN + BPAD) + bc) * 2u,
                   &g_wb[(size_t)(k0 + br0 + 16) * NCOL + bn + bc]);
    };

    // Prologue: stage 0 <- k=0
    load_tiles(0, 0);
    CP_COMMIT();

    const int NITER = FEAT / BKT;   // 64
    for (int it = 0; it < NITER; it++) {
        const int s = it & 1;
        // Prefetch next tile into the other stage (empty commit on last iter
        // keeps the wait_group accounting uniform).
        if (it + 1 < NITER) load_tiles((it + 1) * BKT, s ^ 1);
        CP_COMMIT();
        CP_WAIT1();          // stage s group complete
        __syncthreads();     // make stage s visible to all warps

        const uint32_t abase = a_smem0 + s * a_stage;
        const uint32_t bbase = b_smem0 + s * b_stage;

#pragma unroll
        for (int kk = 0; kk < 2; kk++) {   // two k16 steps inside BK=32
            uint32_t afr[2][4];
            uint32_t bfr[8][2];
#pragma unroll
            for (int mt = 0; mt < 2; mt++) {
                int row = wm + mt * 16 + (lane & 15);
                int col = kk * 16 + (lane >> 4) * 8;
                uint32_t addr = abase + (uint32_t)(row * (BKT + APAD) + col) * 2u;
                asm volatile(
                    "ldmatrix.sync.aligned.m8n8.x4.shared.b16 {%0,%1,%2,%3}, [%4];"
                    : "=r"(afr[mt][0]), "=r"(afr[mt][1]),
                      "=r"(afr[mt][2]), "=r"(afr[mt][3])
                    : "r"(addr));
            }
#pragma unroll
            for (int nt = 0; nt < 8; nt++) {
                int krow = kk * 16 + (lane & 15);
                int col  = wn + nt * 8;
                uint32_t addr = bbase + (uint32_t)(krow * (BN + BPAD) + col) * 2u;
                asm volatile(
                    "ldmatrix.sync.aligned.m8n8.x2.trans.shared.b16 {%0,%1}, [%2];"
                    : "=r"(bfr[nt][0]), "=r"(bfr[nt][1])
                    : "r"(addr));
            }
#pragma unroll
            for (int mt = 0; mt < 2; mt++)
#pragma unroll
                for (int nt = 0; nt < 8; nt++)
                    asm volatile(
                        "mma.sync.aligned.m16n8k16.row.col.f32.bf16.bf16.f32 "
                        "{%0,%1,%2,%3}, {%4,%5,%6,%7}, {%8,%9}, {%0,%1,%2,%3};"
                        : "+f"(acc[mt][nt][0]), "+f"(acc[mt][nt][1]),
                          "+f"(acc[mt][nt][2]), "+f"(acc[mt][nt][3])
                        : "r"(afr[mt][0]), "r"(afr[mt][1]),
                          "r"(afr[mt][2]), "r"(afr[mt][3]),
                          "r"(bfr[nt][0]), "r"(bfr[nt][1]));
        }
        // Next iteration's cp.async overwrites the stage we just computed on;
        // all warps must be done reading it first.
        __syncthreads();
    }

    // ---- epilogue: write fp32 M ----
#pragma unroll
    for (int mt = 0; mt < 2; mt++) {
        int row = bm + wm + mt * 16 + (lane >> 2);
#pragma unroll
        for (int nt = 0; nt < 8; nt++) {
            int col = bn + wn + nt * 8 + (lane & 3) * 2;
            float* p0 = &g_M[(size_t)row * NCOL + col];
            p0[0] = acc[mt][nt][0];
            p0[1] = acc[mt][nt][1];
            float* p1 = &g_M[(size_t)(row + 8) * NCOL + col];
            p1[0] = acc[mt][nt][2];
            p1[1] = acc[mt][nt][3];
        }
    }
}

// ---------------------------------------------------------------------------
// Kernel 3: per-batch pairwise L1 + exp-kernel sum.
// One block per batch row; thread i owns kernel-slot i.
// exp(-norm) predicated on norm < 25: dropped terms are each < 1.4e-11 while
// Os >= 1 (diagonal), so induced rel err < 2e-9 — removes ~all MUFU traffic
// (33.5M unpredicated exps would cost ~220us at MUFU rt=8/SMSP).
// ---------------------------------------------------------------------------
__global__ __launch_bounds__(128) void pairwise_kernel(float* __restrict__ out) {
    __shared__ float s[NKERN * NDIM];   // 8 KB
    const int b = blockIdx.x;
    const int t = threadIdx.x;
    const float* Mb = g_M + (size_t)b * NCOL;

#pragma unroll
    for (int i = t; i < 512; i += 128)
        reinterpret_cast<float4*>(s)[i] =
            reinterpret_cast<const float4*>(Mb)[i];
    __syncthreads();

    float mi[NDIM];
#pragma unroll
    for (int d = 0; d < NDIM; d++) mi[d] = s[t * NDIM + d];

    float accum = 0.0f;
#pragma unroll 4
    for (int j = 0; j < NKERN; j++) {
        const float4* sj = reinterpret_cast<const float4*>(s + j * NDIM);
        float norm = 0.0f;
#pragma unroll
        for (int q = 0; q < 4; q++) {
            float4 v = sj[q];   // broadcast LDS.128 (uniform address)
            norm += fabsf(mi[q * 4 + 0] - v.x);
            norm += fabsf(mi[q * 4 + 1] - v.y);
            norm += fabsf(mi[q * 4 + 2] - v.z);
            norm += fabsf(mi[q * 4 + 3] - v.w);
        }
        if (norm < 25.0f) accum += __expf(-norm);
    }
    out[b * NKERN + t] = accum;
}

// ---------------------------------------------------------------------------
// Launcher (graph-capturable: kernel launches only)
// ---------------------------------------------------------------------------
extern "C" void kernel_launch(void* const* d_in, const int* in_sizes, int n_in,
                              void* d_out, int out_size) {
    const float* x = (const float*)d_in[0];   // [2048, 2048]
    const float* W = (const float*)d_in[1];   // [2048, 2048]
    float* out = (float*)d_out;               // [2048, 128]

    cvt_kernel<<<4096, 256>>>(x, W);

    dim3 grid(NCOL / BN, BATCH / BM);         // 16 x 16
    gemm_kernel<<<grid, 256>>>();

    pairwise_kernel<<<BATCH, 128>>>(out);
}

// round 5
// speedup vs baseline: 1.0987x; 1.0987x over previous
#include <cuda_runtime.h>
#include <cuda_bf16.h>
#include <cuda_fp16.h>
#include <cstdint>

// Problem constants
#define BATCH 2048
#define FEAT  2048
#define NKERN 128
#define NDIM  16
#define NCOL  (NKERN * NDIM)   // 2048

// ---------------------------------------------------------------------------
// Scratch (__device__ globals; no allocations allowed)
// ---------------------------------------------------------------------------
__device__ __nv_bfloat16 g_xb[(size_t)BATCH * FEAT];   // 8 MB
__device__ __nv_bfloat16 g_wb[(size_t)FEAT * NCOL];    // 8 MB
__device__ __half        g_Mh[(size_t)BATCH * NCOL];   // 8 MB (fp16 M)

// ---------------------------------------------------------------------------
// Kernel 1: fp32 -> bf16 conversion, 2 float4 per tensor per thread (MLP=4)
// ---------------------------------------------------------------------------
__global__ __launch_bounds__(256) void cvt_kernel(const float* __restrict__ x,
                                                  const float* __restrict__ W) {
    const int idx = blockIdx.x * blockDim.x + threadIdx.x;    // 0 .. 524287
    const int idx2 = idx + 524288;                            // second half
    const float4* fx = reinterpret_cast<const float4*>(x);
    const float4* fw = reinterpret_cast<const float4*>(W);
    // batch the loads (4 independent LDG.128 in flight)
    const float4 vx0 = fx[idx];
    const float4 vx1 = fx[idx2];
    const float4 vw0 = fw[idx];
    const float4 vw1 = fw[idx2];

    __nv_bfloat162* px = reinterpret_cast<__nv_bfloat162*>(g_xb);
    __nv_bfloat162* pw = reinterpret_cast<__nv_bfloat162*>(g_wb);
    px[2 * idx + 0]  = __floats2bfloat162_rn(vx0.x, vx0.y);
    px[2 * idx + 1]  = __floats2bfloat162_rn(vx0.z, vx0.w);
    px[2 * idx2 + 0] = __floats2bfloat162_rn(vx1.x, vx1.y);
    px[2 * idx2 + 1] = __floats2bfloat162_rn(vx1.z, vx1.w);
    pw[2 * idx + 0]  = __floats2bfloat162_rn(vw0.x, vw0.y);
    pw[2 * idx + 1]  = __floats2bfloat162_rn(vw0.z, vw0.w);
    pw[2 * idx2 + 0] = __floats2bfloat162_rn(vw1.x, vw1.y);
    pw[2 * idx2 + 1] = __floats2bfloat162_rn(vw1.z, vw1.w);
}

// ---------------------------------------------------------------------------
// Kernel 2: bf16 tensor-core GEMM, 3-stage cp.async pipeline, 1 barrier/iter.
// Tile BM=128, BN=128, BK=32, 256 threads (8 warps), warp tile 32x64.
// Output written directly as fp16 (pairwise consumes fp16).
// ---------------------------------------------------------------------------
#define BM   128
#define BN   128
#define BKT  32
#define APAD 8        // As row stride 40 bf16 (80 B)  -> conflict-free ldmatrix
#define BPAD 8        // Bs row stride 136 bf16 (272 B)-> conflict-free trans
#define NSTAGE 3

#define A_STAGE_BYTES (BM * (BKT + APAD) * 2)   // 10240
#define B_STAGE_BYTES (BKT * (BN + BPAD) * 2)   // 8704
#define GEMM_SMEM (NSTAGE * (A_STAGE_BYTES + B_STAGE_BYTES))  // 56832

__device__ __forceinline__ uint32_t smem_u32(const void* p) {
    uint32_t a;
    asm("{ .reg .u64 t; cvta.to.shared.u64 t, %1; cvt.u32.u64 %0, t; }"
        : "=r"(a) : "l"(p));
    return a;
}

__device__ __forceinline__ void cp_async16(uint32_t smem, const void* gmem) {
    asm volatile("cp.async.cg.shared.global [%0], [%1], 16;\n"
                 :: "r"(smem), "l"(gmem));
}
#define CP_COMMIT()  asm volatile("cp.async.commit_group;\n" ::: "memory")
#define CP_WAIT1()   asm volatile("cp.async.wait_group 1;\n" ::: "memory")

__global__ __launch_bounds__(256) void gemm_kernel() {
    extern __shared__ char smem_raw[];

    const int tid  = threadIdx.x;
    const int warp = tid >> 5;
    const int lane = tid & 31;
    const int wm   = (warp & 3) * 32;   // warp row offset in block tile
    const int wn   = (warp >> 2) * 64;  // warp col offset in block tile
    const int bm   = blockIdx.y * BM;
    const int bn   = blockIdx.x * BN;

    const uint32_t a_smem0 = smem_u32(smem_raw);
    const uint32_t b_smem0 = a_smem0 + NSTAGE * A_STAGE_BYTES;

    // Per-thread load coordinates (fixed across iterations)
    const int ar0 = tid >> 2;            // A rows: ar0, ar0+64
    const int ac  = (tid & 3) * 8;
    const int br0 = tid >> 4;            // B rows: br0, br0+16
    const int bc  = (tid & 15) * 8;

    float acc[2][8][4];
#pragma unroll
    for (int mt = 0; mt < 2; mt++)
#pragma unroll
        for (int nt = 0; nt < 8; nt++)
#pragma unroll
            for (int q = 0; q < 4; q++) acc[mt][nt][q] = 0.0f;

    auto load_tiles = [&](int k0, int s) {
        const uint32_t abase = a_smem0 + s * A_STAGE_BYTES;
        const uint32_t bbase = b_smem0 + s * B_STAGE_BYTES;
        cp_async16(abase + (uint32_t)(ar0 * (BKT + APAD) + ac) * 2u,
                   &g_xb[(size_t)(bm + ar0) * FEAT + k0 + ac]);
        cp_async16(abase + (uint32_t)((ar0 + 64) * (BKT + APAD) + ac) * 2u,
                   &g_xb[(size_t)(bm + ar0 + 64) * FEAT + k0 + ac]);
        cp_async16(bbase + (uint32_t)(br0 * (BN + BPAD) + bc) * 2u,
                   &g_wb[(size_t)(k0 + br0) * NCOL + bn + bc]);
        cp_async16(bbase + (uint32_t)((br0 + 16) * (BN + BPAD) + bc) * 2u,
                   &g_wb[(size_t)(k0 + br0 + 16) * NCOL + bn + bc]);
    };

    // Prologue: slots 0 and 1
    load_tiles(0, 0);
    CP_COMMIT();
    load_tiles(BKT, 1);
    CP_COMMIT();

    const int NITER = FEAT / BKT;   // 64
    int slot = 0;
    for (int it = 0; it < NITER; it++) {
        CP_WAIT1();          // group for 'slot' complete
        __syncthreads();     // data visible to all warps; previous slot free

        // Prefetch it+2 into the slot freed by iteration it-1
        if (it + 2 < NITER) {
            int ps = slot - 1; if (ps < 0) ps += NSTAGE;   // (it+2) % 3
            load_tiles((it + 2) * BKT, ps);
        }
        CP_COMMIT();         // commit every iter to keep group accounting uniform

        const uint32_t abase = a_smem0 + slot * A_STAGE_BYTES;
        const uint32_t bbase = b_smem0 + slot * B_STAGE_BYTES;

#pragma unroll
        for (int kk = 0; kk < 2; kk++) {   // two k16 steps inside BK=32
            uint32_t afr[2][4];
            uint32_t bfr[8][2];
#pragma unroll
            for (int mt = 0; mt < 2; mt++) {
                int row = wm + mt * 16 + (lane & 15);
                int col = kk * 16 + (lane >> 4) * 8;
                uint32_t addr = abase + (uint32_t)(row * (BKT + APAD) + col) * 2u;
                asm volatile(
                    "ldmatrix.sync.aligned.m8n8.x4.shared.b16 {%0,%1,%2,%3}, [%4];"
                    : "=r"(afr[mt][0]), "=r"(afr[mt][1]),
                      "=r"(afr[mt][2]), "=r"(afr[mt][3])
                    : "r"(addr));
            }
            // B: 4x ldmatrix.x4.trans, each covers two nt's (16 cols x 16 k)
#pragma unroll
            for (int ntp = 0; ntp < 4; ntp++) {
                int krow = kk * 16 + ((lane >> 3) & 1) * 8 + (lane & 7);
                int col  = wn + ntp * 16 + (lane >> 4) * 8;
                uint32_t addr = bbase + (uint32_t)(krow * (BN + BPAD) + col) * 2u;
                asm volatile(
                    "ldmatrix.sync.aligned.m8n8.x4.trans.shared.b16 "
                    "{%0,%1,%2,%3}, [%4];"
                    : "=r"(bfr[2 * ntp][0]),     "=r"(bfr[2 * ntp][1]),
                      "=r"(bfr[2 * ntp + 1][0]), "=r"(bfr[2 * ntp + 1][1])
                    : "r"(addr));
            }
#pragma unroll
            for (int mt = 0; mt < 2; mt++)
#pragma unroll
                for (int nt = 0; nt < 8; nt++)
                    asm volatile(
                        "mma.sync.aligned.m16n8k16.row.col.f32.bf16.bf16.f32 "
                        "{%0,%1,%2,%3}, {%4,%5,%6,%7}, {%8,%9}, {%0,%1,%2,%3};"
                        : "+f"(acc[mt][nt][0]), "+f"(acc[mt][nt][1]),
                          "+f"(acc[mt][nt][2]), "+f"(acc[mt][nt][3])
                        : "r"(afr[mt][0]), "r"(afr[mt][1]),
                          "r"(afr[mt][2]), "r"(afr[mt][3]),
                          "r"(bfr[nt][0]), "r"(bfr[nt][1]));
        }
        slot++; if (slot == NSTAGE) slot = 0;
    }

    // ---- epilogue: write fp16 M (half2 packs the 2 adjacent cols) ----
    __half2* Mh2 = reinterpret_cast<__half2*>(g_Mh);
#pragma unroll
    for (int mt = 0; mt < 2; mt++) {
        int row = bm + wm + mt * 16 + (lane >> 2);
#pragma unroll
        for (int nt = 0; nt < 8; nt++) {
            int col = bn + wn + nt * 8 + (lane & 3) * 2;
            Mh2[((size_t)row * NCOL + col) >> 1] =
                __floats2half2_rn(acc[mt][nt][0], acc[mt][nt][1]);
            Mh2[((size_t)(row + 8) * NCOL + col) >> 1] =
                __floats2half2_rn(acc[mt][nt][2], acc[mt][nt][3]);
        }
    }
}

// ---------------------------------------------------------------------------
// Kernel 3: per-batch pairwise L1 + exp-kernel sum, fp16x2 arithmetic.
// One block per batch row; thread i owns kernel-slot i.
// Safety: measured rel_err 5e-9 with bf16 GEMM implies no off-diagonal pair
// has norm < ~16; fp16 norm error (<0.08 abs) perturbs only terms < e^-16,
// inducing < 1e-8 output error. exp predicated on norm < 25 as before
// (dropped terms < 1.4e-11 each vs Os >= 1 diagonal).
// ---------------------------------------------------------------------------
__global__ __launch_bounds__(128) void pairwise_kernel(float* __restrict__ out) {
    __shared__ __align__(16) __half2 s[NKERN * 8];   // 128 rows x 16 halves = 4 KB
    const int b = blockIdx.x;
    const int t = threadIdx.x;

    // cooperative load: 256 uint4 (one row of M = 2048 halves)
    const uint4* src = reinterpret_cast<const uint4*>(g_Mh + (size_t)b * NCOL);
    uint4* dst = reinterpret_cast<uint4*>(s);
    dst[t]       = src[t];
    dst[t + 128] = src[t + 128];
    __syncthreads();

    // own row in registers (8 half2)
    __half2 mi[8];
    {
        uint4 q0 = reinterpret_cast<const uint4*>(s)[2 * t];
        uint4 q1 = reinterpret_cast<const uint4*>(s)[2 * t + 1];
        mi[0] = *reinterpret_cast<__half2*>(&q0.x);
        mi[1] = *reinterpret_cast<__half2*>(&q0.y);
        mi[2] = *reinterpret_cast<__half2*>(&q0.z);
        mi[3] = *reinterpret_cast<__half2*>(&q0.w);
        mi[4] = *reinterpret_cast<__half2*>(&q1.x);
        mi[5] = *reinterpret_cast<__half2*>(&q1.y);
        mi[6] = *reinterpret_cast<__half2*>(&q1.z);
        mi[7] = *reinterpret_cast<__half2*>(&q1.w);
    }

    const __half hthr = __float2half(25.0f);
    float accum = 0.0f;
#pragma unroll 4
    for (int j = 0; j < NKERN; j++) {
        // broadcast LDS.128 x2 (uniform address across warp)
        uint4 q0 = reinterpret_cast<const uint4*>(s)[2 * j];
        uint4 q1 = reinterpret_cast<const uint4*>(s)[2 * j + 1];
        __half2 v0 = *reinterpret_cast<__half2*>(&q0.x);
        __half2 v1 = *reinterpret_cast<__half2*>(&q0.y);
        __half2 v2 = *reinterpret_cast<__half2*>(&q0.z);
        __half2 v3 = *reinterpret_cast<__half2*>(&q0.w);
        __half2 v4 = *reinterpret_cast<__half2*>(&q1.x);
        __half2 v5 = *reinterpret_cast<__half2*>(&q1.y);
        __half2 v6 = *reinterpret_cast<__half2*>(&q1.z);
        __half2 v7 = *reinterpret_cast<__half2*>(&q1.w);

        __half2 d0 = __habs2(__hsub2(mi[0], v0));
        __half2 d1 = __habs2(__hsub2(mi[1], v1));
        __half2 d2 = __habs2(__hsub2(mi[2], v2));
        __half2 d3 = __habs2(__hsub2(mi[3], v3));
        __half2 d4 = __habs2(__hsub2(mi[4], v4));
        __half2 d5 = __habs2(__hsub2(mi[5], v5));
        __half2 d6 = __habs2(__hsub2(mi[6], v6));
        __half2 d7 = __habs2(__hsub2(mi[7], v7));

        __half2 s01 = __hadd2(d0, d1);
        __half2 s23 = __hadd2(d2, d3);
        __half2 s45 = __hadd2(d4, d5);
        __half2 s67 = __hadd2(d6, d7);
        __half2 s03 = __hadd2(s01, s23);
        __half2 s47 = __hadd2(s45, s67);
        __half2 n2  = __hadd2(s03, s47);
        __half  n   = __hadd(__low2half(n2), __high2half(n2));

        if (__hlt(n, hthr)) accum += __expf(-__half2float(n));
    }
    out[b * NKERN + t] = accum;
}

// ---------------------------------------------------------------------------
// Launcher (graph-capturable: kernel launches + one attribute set)
// ---------------------------------------------------------------------------
extern "C" void kernel_launch(void* const* d_in, const int* in_sizes, int n_in,
                              void* d_out, int out_size) {
    const float* x = (const float*)d_in[0];   // [2048, 2048]
    const float* W = (const float*)d_in[1];   // [2048, 2048]
    float* out = (float*)d_out;               // [2048, 128]

    // opt-in >48KB dynamic smem (idempotent, non-stream API)
    cudaFuncSetAttribute(gemm_kernel,
                         cudaFuncAttributeMaxDynamicSharedMemorySize, GEMM_SMEM);

    cvt_kernel<<<2048, 256>>>(x, W);

    dim3 grid(NCOL / BN, BATCH / BM);         // 16 x 16
    gemm_kernel<<<grid, 256, GEMM_SMEM>>>();

    pairwise_kernel<<<BATCH, 128>>>(out);
}

// round 8
// speedup vs baseline: 1.1343x; 1.0324x over previous
#include <cuda_runtime.h>
#include <cuda_fp16.h>
#include <cstdint>

// Problem constants
#define BATCH 2048
#define FEAT  2048
#define NKERN 128
#define NDIM  16
#define NCOL  (NKERN * NDIM)   // 2048

// ---------------------------------------------------------------------------
// Scratch (__device__ globals; no allocations allowed)
// ---------------------------------------------------------------------------
__device__ __half g_xh[(size_t)BATCH * FEAT];   // 8 MB  x  in fp16 [B][F]
__device__ __half g_wh[(size_t)FEAT * NCOL];    // 8 MB  W  in fp16 [F][N]
__device__ __half g_Mh[(size_t)BATCH * NCOL];   // 8 MB  M  in fp16

// ---------------------------------------------------------------------------
// Kernel 1: fp32 -> fp16 for x and W, fully vectorized (LDG.128 / STG.128)
// ---------------------------------------------------------------------------
__global__ __launch_bounds__(256) void cvt_kernel(const float* __restrict__ x,
                                                  const float* __restrict__ W) {
    const int idx = blockIdx.x * blockDim.x + threadIdx.x;   // 0..524287
    const float4* fx = reinterpret_cast<const float4*>(x);
    const float4* fw = reinterpret_cast<const float4*>(W);
    const float4 a0 = fx[2 * idx + 0];
    const float4 a1 = fx[2 * idx + 1];
    const float4 b0 = fw[2 * idx + 0];
    const float4 b1 = fw[2 * idx + 1];

    __half2 h;
    uint4 u;
    h = __floats2half2_rn(a0.x, a0.y); u.x = *reinterpret_cast<uint32_t*>(&h);
    h = __floats2half2_rn(a0.z, a0.w); u.y = *reinterpret_cast<uint32_t*>(&h);
    h = __floats2half2_rn(a1.x, a1.y); u.z = *reinterpret_cast<uint32_t*>(&h);
    h = __floats2half2_rn(a1.z, a1.w); u.w = *reinterpret_cast<uint32_t*>(&h);
    reinterpret_cast<uint4*>(g_xh)[idx] = u;

    h = __floats2half2_rn(b0.x, b0.y); u.x = *reinterpret_cast<uint32_t*>(&h);
    h = __floats2half2_rn(b0.z, b0.w); u.y = *reinterpret_cast<uint32_t*>(&h);
    h = __floats2half2_rn(b1.x, b1.y); u.z = *reinterpret_cast<uint32_t*>(&h);
    h = __floats2half2_rn(b1.z, b1.w); u.w = *reinterpret_cast<uint32_t*>(&h);
    reinterpret_cast<uint4*>(g_wh)[idx] = u;
}

// ---------------------------------------------------------------------------
// Kernel 2: fp16 tensor-core GEMM (fp16 accumulate), 3-stage cp.async
// pipeline, 1 barrier/iter. Tile BM=128, BN=128, BK=32, 256 threads (8 warps),
// warp tile 32x64. D written as packed fp16 directly from the accumulator.
// fp16-acc halves acc registers (32 u32) -> ~90 regs -> 2 CTAs/SM resident.
// ---------------------------------------------------------------------------
#define BM   128
#define BN   128
#define BKT  32
#define APAD 8        // As row stride 40 fp16 (80 B)  -> conflict-free ldmatrix
#define BPAD 8        // Bs row stride 136 fp16 (272 B)-> conflict-free trans
#define NSTAGE 3

#define A_STAGE_BYTES (BM * (BKT + APAD) * 2)   // 10240
#define B_STAGE_BYTES (BKT * (BN + BPAD) * 2)   // 8704
#define GEMM_SMEM (NSTAGE * (A_STAGE_BYTES + B_STAGE_BYTES))  // 56832

__device__ __forceinline__ uint32_t smem_u32(const void* p) {
    uint32_t a;
    asm("{ .reg .u64 t; cvta.to.shared.u64 t, %1; cvt.u32.u64 %0, t; }"
        : "=r"(a) : "l"(p));
    return a;
}

__device__ __forceinline__ void cp_async16(uint32_t smem, const void* gmem) {
    asm volatile("cp.async.cg.shared.global [%0], [%1], 16;\n"
                 :: "r"(smem), "l"(gmem));
}
#define CP_COMMIT()  asm volatile("cp.async.commit_group;\n" ::: "memory")
#define CP_WAIT1()   asm volatile("cp.async.wait_group 1;\n" ::: "memory")

__global__ __launch_bounds__(256) void gemm_kernel() {
    extern __shared__ char smem_raw[];

    const int tid  = threadIdx.x;
    const int warp = tid >> 5;
    const int lane = tid & 31;
    const int wm   = (warp & 3) * 32;   // warp row offset in block tile
    const int wn   = (warp >> 2) * 64;  // warp col offset in block tile
    const int bm   = blockIdx.y * BM;
    const int bn   = blockIdx.x * BN;

    const uint32_t a_smem0 = smem_u32(smem_raw);
    const uint32_t b_smem0 = a_smem0 + NSTAGE * A_STAGE_BYTES;

    // Per-thread load coordinates (fixed across iterations)
    const int ar0 = tid >> 2;            // A rows: ar0, ar0+64
    const int ac  = (tid & 3) * 8;
    const int br0 = tid >> 4;            // B rows: br0, br0+16
    const int bc  = (tid & 15) * 8;

    // fp16 accumulators: 2 u32 (= 4 halves) per mma
    uint32_t acc[2][8][2];
#pragma unroll
    for (int mt = 0; mt < 2; mt++)
#pragma unroll
        for (int nt = 0; nt < 8; nt++) { acc[mt][nt][0] = 0u; acc[mt][nt][1] = 0u; }

    auto load_tiles = [&](int k0, int s) {
        const uint32_t abase = a_smem0 + s * A_STAGE_BYTES;
        const uint32_t bbase = b_smem0 + s * B_STAGE_BYTES;
        cp_async16(abase + (uint32_t)(ar0 * (BKT + APAD) + ac) * 2u,
                   &g_xh[(size_t)(bm + ar0) * FEAT + k0 + ac]);
        cp_async16(abase + (uint32_t)((ar0 + 64) * (BKT + APAD) + ac) * 2u,
                   &g_xh[(size_t)(bm + ar0 + 64) * FEAT + k0 + ac]);
        cp_async16(bbase + (uint32_t)(br0 * (BN + BPAD) + bc) * 2u,
                   &g_wh[(size_t)(k0 + br0) * NCOL + bn + bc]);
        cp_async16(bbase + (uint32_t)((br0 + 16) * (BN + BPAD) + bc) * 2u,
                   &g_wh[(size_t)(k0 + br0 + 16) * NCOL + bn + bc]);
    };

    // Prologue: slots 0 and 1
    load_tiles(0, 0);
    CP_COMMIT();
    load_tiles(BKT, 1);
    CP_COMMIT();

    const int NITER = FEAT / BKT;   // 64
    int slot = 0;
    for (int it = 0; it < NITER; it++) {
        CP_WAIT1();          // group for 'slot' complete
        __syncthreads();     // data visible; previous slot free for refill

        if (it + 2 < NITER) {
            int ps = slot - 1; if (ps < 0) ps += NSTAGE;   // (it+2) % 3
            load_tiles((it + 2) * BKT, ps);
        }
        CP_COMMIT();         // unconditional: uniform group accounting

        const uint32_t abase = a_smem0 + slot * A_STAGE_BYTES;
        const uint32_t bbase = b_smem0 + slot * B_STAGE_BYTES;

#pragma unroll
        for (int kk = 0; kk < 2; kk++) {   // two k16 steps inside BK=32
            uint32_t afr[2][4];
            uint32_t bfr[8][2];
#pragma unroll
            for (int mt = 0; mt < 2; mt++) {
                int row = wm + mt * 16 + (lane & 15);
                int col = kk * 16 + (lane >> 4) * 8;
                uint32_t addr = abase + (uint32_t)(row * (BKT + APAD) + col) * 2u;
                asm volatile(
                    "ldmatrix.sync.aligned.m8n8.x4.shared.b16 {%0,%1,%2,%3}, [%4];"
                    : "=r"(afr[mt][0]), "=r"(afr[mt][1]),
                      "=r"(afr[mt][2]), "=r"(afr[mt][3])
                    : "r"(addr));
            }
            // B: 4x ldmatrix.x4.trans, each covers two nt's (16 cols x 16 k)
#pragma unroll
            for (int ntp = 0; ntp < 4; ntp++) {
                int krow = kk * 16 + ((lane >> 3) & 1) * 8 + (lane & 7);
                int col  = wn + ntp * 16 + (lane >> 4) * 8;
                uint32_t addr = bbase + (uint32_t)(krow * (BN + BPAD) + col) * 2u;
                asm volatile(
                    "ldmatrix.sync.aligned.m8n8.x4.trans.shared.b16 "
                    "{%0,%1,%2,%3}, [%4];"
                    : "=r"(bfr[2 * ntp][0]),     "=r"(bfr[2 * ntp][1]),
                      "=r"(bfr[2 * ntp + 1][0]), "=r"(bfr[2 * ntp + 1][1])
                    : "r"(addr));
            }
#pragma unroll
            for (int mt = 0; mt < 2; mt++)
#pragma unroll
                for (int nt = 0; nt < 8; nt++)
                    asm volatile(
                        "mma.sync.aligned.m16n8k16.row.col.f16.f16.f16.f16 "
                        "{%0,%1}, {%2,%3,%4,%5}, {%6,%7}, {%0,%1};"
                        : "+r"(acc[mt][nt][0]), "+r"(acc[mt][nt][1])
                        : "r"(afr[mt][0]), "r"(afr[mt][1]),
                          "r"(afr[mt][2]), "r"(afr[mt][3]),
                          "r"(bfr[nt][0]), "r"(bfr[nt][1]));
        }
        slot++; if (slot == NSTAGE) slot = 0;
    }

    // ---- epilogue: acc regs are already packed half2 {col, col+1} ----
    // c0 -> row (lane>>2), c1 -> row+8, cols = wn + nt*8 + (lane&3)*2
    uint32_t* Mh32 = reinterpret_cast<uint32_t*>(g_Mh);
#pragma unroll
    for (int mt = 0; mt < 2; mt++) {
        int row = bm + wm + mt * 16 + (lane >> 2);
#pragma unroll
        for (int nt = 0; nt < 8; nt++) {
            int col = bn + wn + nt * 8 + (lane & 3) * 2;
            Mh32[((size_t)row * NCOL + col) >> 1]       = acc[mt][nt][0];
            Mh32[((size_t)(row + 8) * NCOL + col) >> 1] = acc[mt][nt][1];
        }
    }
}

// ---------------------------------------------------------------------------
// Kernel 3: per-batch pairwise L1 + exp-kernel sum, fp16x2 (fma-pipe bound).
// exp predicated on norm < 25: measured rel_err 5e-9 (round 2 config) proves
// no off-diagonal norm below ~16, so dropped terms are < 1.4e-11 each while
// Os >= 1 (diagonal pair is exactly 0 -> exp(0)=1). fp16 norm error (<0.1)
// perturbs only e^-16-scale terms -> output rel err ~1e-7.
// ---------------------------------------------------------------------------
__global__ __launch_bounds__(128) void pairwise_kernel(float* __restrict__ out) {
    __shared__ __align__(16) __half2 s[NKERN * 8];   // 4 KB
    const int b = blockIdx.x;
    const int t = threadIdx.x;

    const uint4* src = reinterpret_cast<const uint4*>(g_Mh + (size_t)b * NCOL);
    uint4* dst = reinterpret_cast<uint4*>(s);
    dst[t]       = src[t];
    dst[t + 128] = src[t + 128];
    __syncthreads();

    __half2 mi[8];
    {
        uint4 q0 = reinterpret_cast<const uint4*>(s)[2 * t];
        uint4 q1 = reinterpret_cast<const uint4*>(s)[2 * t + 1];
        mi[0] = *reinterpret_cast<__half2*>(&q0.x);
        mi[1] = *reinterpret_cast<__half2*>(&q0.y);
        mi[2] = *reinterpret_cast<__half2*>(&q0.z);
        mi[3] = *reinterpret_cast<__half2*>(&q0.w);
        mi[4] = *reinterpret_cast<__half2*>(&q1.x);
        mi[5] = *reinterpret_cast<__half2*>(&q1.y);
        mi[6] = *reinterpret_cast<__half2*>(&q1.z);
        mi[7] = *reinterpret_cast<__half2*>(&q1.w);
    }

    const __half hthr = __float2half(25.0f);
    float accum = 0.0f;
#pragma unroll 4
    for (int j = 0; j < NKERN; j++) {
        uint4 q0 = reinterpret_cast<const uint4*>(s)[2 * j];
        uint4 q1 = reinterpret_cast<const uint4*>(s)[2 * j + 1];
        __half2 v0 = *reinterpret_cast<__half2*>(&q0.x);
        __half2 v1 = *reinterpret_cast<__half2*>(&q0.y);
        __half2 v2 = *reinterpret_cast<__half2*>(&q0.z);
        __half2 v3 = *reinterpret_cast<__half2*>(&q0.w);
        __half2 v4 = *reinterpret_cast<__half2*>(&q1.x);
        __half2 v5 = *reinterpret_cast<__half2*>(&q1.y);
        __half2 v6 = *reinterpret_cast<__half2*>(&q1.z);
        __half2 v7 = *reinterpret_cast<__half2*>(&q1.w);

        __half2 d0 = __habs2(__hsub2(mi[0], v0));
        __half2 d1 = __habs2(__hsub2(mi[1], v1));
        __half2 d2 = __habs2(__hsub2(mi[2], v2));
        __half2 d3 = __habs2(__hsub2(mi[3], v3));
        __half2 d4 = __habs2(__hsub2(mi[4], v4));
        __half2 d5 = __habs2(__hsub2(mi[5], v5));
        __half2 d6 = __habs2(__hsub2(mi[6], v6));
        __half2 d7 = __habs2(__hsub2(mi[7], v7));

        __half2 s01 = __hadd2(d0, d1);
        __half2 s23 = __hadd2(d2, d3);
        __half2 s45 = __hadd2(d4, d5);
        __half2 s67 = __hadd2(d6, d7);
        __half2 s03 = __hadd2(s01, s23);
        __half2 s47 = __hadd2(s45, s67);
        __half2 n2  = __hadd2(s03, s47);
        __half  n   = __hadd(__low2half(n2), __high2half(n2));

        if (__hlt(n, hthr)) accum += __expf(-__half2float(n));
    }
    out[b * NKERN + t] = accum;
}

// ---------------------------------------------------------------------------
// Launcher (graph-capturable: kernel launches + attribute set)
// ---------------------------------------------------------------------------
extern "C" void kernel_launch(void* const* d_in, const int* in_sizes, int n_in,
                              void* d_out, int out_size) {
    const float* x = (const float*)d_in[0];   // [2048, 2048]
    const float* W = (const float*)d_in[1];   // [2048, 2048]
    float* out = (float*)d_out;               // [2048, 128]

    cudaFuncSetAttribute(gemm_kernel,
                         cudaFuncAttributeMaxDynamicSharedMemorySize, GEMM_SMEM);

    cvt_kernel<<<2048, 256>>>(x, W);

    dim3 grid(NCOL / BN, BATCH / BM);         // 16 x 16
    gemm_kernel<<<grid, 256, GEMM_SMEM>>>();

    pairwise_kernel<<<BATCH, 128>>>(out);
}

// round 10
// speedup vs baseline: 1.3091x; 1.1540x over previous
#include <cuda_runtime.h>
#include <cuda_fp16.h>
#include <cstdint>

// Problem constants
#define BATCH 2048
#define FEAT  2048
#define NKERN 128
#define NDIM  16
#define NCOL  (NKERN * NDIM)   // 2048

// ---------------------------------------------------------------------------
// Scratch (__device__ globals; no allocations allowed)
// ---------------------------------------------------------------------------
__device__ __half g_xh[(size_t)BATCH * FEAT];   // 8 MB  x  in fp16 [B][F]
__device__ __half g_wh[(size_t)FEAT * NCOL];    // 8 MB  W  in fp16 [F][N]
__device__ __half g_Mh[(size_t)BATCH * NCOL];   // 8 MB  M  in fp16

// ---------------------------------------------------------------------------
// Kernel 1: fp32 -> fp16 for x and W (unchanged from round 8: 9.4us)
// ---------------------------------------------------------------------------
__global__ __launch_bounds__(256) void cvt_kernel(const float* __restrict__ x,
                                                  const float* __restrict__ W) {
    const int idx = blockIdx.x * blockDim.x + threadIdx.x;   // 0..524287
    const float4* fx = reinterpret_cast<const float4*>(x);
    const float4* fw = reinterpret_cast<const float4*>(W);
    const float4 a0 = fx[2 * idx + 0];
    const float4 a1 = fx[2 * idx + 1];
    const float4 b0 = fw[2 * idx + 0];
    const float4 b1 = fw[2 * idx + 1];

    __half2 h;
    uint4 u;
    h = __floats2half2_rn(a0.x, a0.y); u.x = *reinterpret_cast<uint32_t*>(&h);
    h = __floats2half2_rn(a0.z, a0.w); u.y = *reinterpret_cast<uint32_t*>(&h);
    h = __floats2half2_rn(a1.x, a1.y); u.z = *reinterpret_cast<uint32_t*>(&h);
    h = __floats2half2_rn(a1.z, a1.w); u.w = *reinterpret_cast<uint32_t*>(&h);
    reinterpret_cast<uint4*>(g_xh)[idx] = u;

    h = __floats2half2_rn(b0.x, b0.y); u.x = *reinterpret_cast<uint32_t*>(&h);
    h = __floats2half2_rn(b0.z, b0.w); u.y = *reinterpret_cast<uint32_t*>(&h);
    h = __floats2half2_rn(b1.x, b1.y); u.z = *reinterpret_cast<uint32_t*>(&h);
    h = __floats2half2_rn(b1.z, b1.w); u.w = *reinterpret_cast<uint32_t*>(&h);
    reinterpret_cast<uint4*>(g_wh)[idx] = u;
}

// ---------------------------------------------------------------------------
// Kernel 2: fp16 tensor-core GEMM (fp16 accumulate), 3-stage cp.async
// pipeline, 1 barrier/iter. UNCHANGED from round 8 (measured at the
// mma.sync rate wall ~64-68us; rt(HMMA.16816)=16/SMSP model fits).
// ---------------------------------------------------------------------------
#define BM   128
#define BN   128
#define BKT  32
#define APAD 8
#define BPAD 8
#define NSTAGE 3

#define A_STAGE_BYTES (BM * (BKT + APAD) * 2)   // 10240
#define B_STAGE_BYTES (BKT * (BN + BPAD) * 2)   // 8704
#define GEMM_SMEM (NSTAGE * (A_STAGE_BYTES + B_STAGE_BYTES))  // 56832

__device__ __forceinline__ uint32_t smem_u32(const void* p) {
    uint32_t a;
    asm("{ .reg .u64 t; cvta.to.shared.u64 t, %1; cvt.u32.u64 %0, t; }"
        : "=r"(a) : "l"(p));
    return a;
}

__device__ __forceinline__ void cp_async16(uint32_t smem, const void* gmem) {
    asm volatile("cp.async.cg.shared.global [%0], [%1], 16;\n"
                 :: "r"(smem), "l"(gmem));
}
#define CP_COMMIT()  asm volatile("cp.async.commit_group;\n" ::: "memory")
#define CP_WAIT1()   asm volatile("cp.async.wait_group 1;\n" ::: "memory")

__global__ __launch_bounds__(256) void gemm_kernel() {
    extern __shared__ char smem_raw[];

    const int tid  = threadIdx.x;
    const int warp = tid >> 5;
    const int lane = tid & 31;
    const int wm   = (warp & 3) * 32;
    const int wn   = (warp >> 2) * 64;
    const int bm   = blockIdx.y * BM;
    const int bn   = blockIdx.x * BN;

    const uint32_t a_smem0 = smem_u32(smem_raw);
    const uint32_t b_smem0 = a_smem0 + NSTAGE * A_STAGE_BYTES;

    const int ar0 = tid >> 2;
    const int ac  = (tid & 3) * 8;
    const int br0 = tid >> 4;
    const int bc  = (tid & 15) * 8;

    uint32_t acc[2][8][2];
#pragma unroll
    for (int mt = 0; mt < 2; mt++)
#pragma unroll
        for (int nt = 0; nt < 8; nt++) { acc[mt][nt][0] = 0u; acc[mt][nt][1] = 0u; }

    auto load_tiles = [&](int k0, int s) {
        const uint32_t abase = a_smem0 + s * A_STAGE_BYTES;
        const uint32_t bbase = b_smem0 + s * B_STAGE_BYTES;
        cp_async16(abase + (uint32_t)(ar0 * (BKT + APAD) + ac) * 2u,
                   &g_xh[(size_t)(bm + ar0) * FEAT + k0 + ac]);
        cp_async16(abase + (uint32_t)((ar0 + 64) * (BKT + APAD) + ac) * 2u,
                   &g_xh[(size_t)(bm + ar0 + 64) * FEAT + k0 + ac]);
        cp_async16(bbase + (uint32_t)(br0 * (BN + BPAD) + bc) * 2u,
                   &g_wh[(size_t)(k0 + br0) * NCOL + bn + bc]);
        cp_async16(bbase + (uint32_t)((br0 + 16) * (BN + BPAD) + bc) * 2u,
                   &g_wh[(size_t)(k0 + br0 + 16) * NCOL + bn + bc]);
    };

    load_tiles(0, 0);
    CP_COMMIT();
    load_tiles(BKT, 1);
    CP_COMMIT();

    const int NITER = FEAT / BKT;   // 64
    int slot = 0;
    for (int it = 0; it < NITER; it++) {
        CP_WAIT1();
        __syncthreads();

        if (it + 2 < NITER) {
            int ps = slot - 1; if (ps < 0) ps += NSTAGE;
            load_tiles((it + 2) * BKT, ps);
        }
        CP_COMMIT();

        const uint32_t abase = a_smem0 + slot * A_STAGE_BYTES;
        const uint32_t bbase = b_smem0 + slot * B_STAGE_BYTES;

#pragma unroll
        for (int kk = 0; kk < 2; kk++) {
            uint32_t afr[2][4];
            uint32_t bfr[8][2];
#pragma unroll
            for (int mt = 0; mt < 2; mt++) {
                int row = wm + mt * 16 + (lane & 15);
                int col = kk * 16 + (lane >> 4) * 8;
                uint32_t addr = abase + (uint32_t)(row * (BKT + APAD) + col) * 2u;
                asm volatile(
                    "ldmatrix.sync.aligned.m8n8.x4.shared.b16 {%0,%1,%2,%3}, [%4];"
                    : "=r"(afr[mt][0]), "=r"(afr[mt][1]),
                      "=r"(afr[mt][2]), "=r"(afr[mt][3])
                    : "r"(addr));
            }
#pragma unroll
            for (int ntp = 0; ntp < 4; ntp++) {
                int krow = kk * 16 + ((lane >> 3) & 1) * 8 + (lane & 7);
                int col  = wn + ntp * 16 + (lane >> 4) * 8;
                uint32_t addr = bbase + (uint32_t)(krow * (BN + BPAD) + col) * 2u;
                asm volatile(
                    "ldmatrix.sync.aligned.m8n8.x4.trans.shared.b16 "
                    "{%0,%1,%2,%3}, [%4];"
                    : "=r"(bfr[2 * ntp][0]),     "=r"(bfr[2 * ntp][1]),
                      "=r"(bfr[2 * ntp + 1][0]), "=r"(bfr[2 * ntp + 1][1])
                    : "r"(addr));
            }
#pragma unroll
            for (int mt = 0; mt < 2; mt++)
#pragma unroll
                for (int nt = 0; nt < 8; nt++)
                    asm volatile(
                        "mma.sync.aligned.m16n8k16.row.col.f16.f16.f16.f16 "
                        "{%0,%1}, {%2,%3,%4,%5}, {%6,%7}, {%0,%1};"
                        : "+r"(acc[mt][nt][0]), "+r"(acc[mt][nt][1])
                        : "r"(afr[mt][0]), "r"(afr[mt][1]),
                          "r"(afr[mt][2]), "r"(afr[mt][3]),
                          "r"(bfr[nt][0]), "r"(bfr[nt][1]));
        }
        slot++; if (slot == NSTAGE) slot = 0;
    }

    uint32_t* Mh32 = reinterpret_cast<uint32_t*>(g_Mh);
#pragma unroll
    for (int mt = 0; mt < 2; mt++) {
        int row = bm + wm + mt * 16 + (lane >> 2);
#pragma unroll
        for (int nt = 0; nt < 8; nt++) {
            int col = bn + wn + nt * 8 + (lane & 3) * 2;
            Mh32[((size_t)row * NCOL + col) >> 1]       = acc[mt][nt][0];
            Mh32[((size_t)(row + 8) * NCOL + col) >> 1] = acc[mt][nt][1];
        }
    }
}

// ---------------------------------------------------------------------------
// Kernel 3: pairwise L1 + exp, SYMMETRIC halving.
// Each unordered pair {i,j} computed ONCE: for any pair, exactly one of the
// two circular offsets lies in 1..63 (they sum to 128), so the r=1..63 loop
// emits it once; offset-64 pairs are emitted once by threads t<64.
// exp(-n) credited to both rows: own row in a register, partner row via
// shared atomicAdd — executed only when n<25 (~2% of pairs; ~126 atomics
// spread over 128 addresses -> negligible).
// Dim-major smem layout half2 s2[8][128]: lanes access consecutive j ->
// conflict-free LDS.32. fma-pipe ops per pair: 16 (8 HSUB2 + 7 HADD2 + HADD);
// HABS2 folds to the alu pipe. Work halves vs round 8: ~32us -> ~17us.
// Numerics: same terms, same rounding; atomic order perturbs only 1e-7-scale
// sums. Diagonal exp(0)=1 added as the 1.0f constant.
// ---------------------------------------------------------------------------
__global__ __launch_bounds__(128) void pairwise_kernel(float* __restrict__ out) {
    __shared__ __align__(16) __half2 s2[8][NKERN];   // [dim-pair][kernel] 4KB
    __shared__ float s_acc[NKERN];
    const int b = blockIdx.x;
    const int t = threadIdx.x;

    // Thread t owns kernel-row t: load its 16 halves (2 LDG.128), keep in
    // registers as mi[], and scatter dim-major into smem.
    const uint4* src =
        reinterpret_cast<const uint4*>(g_Mh + (size_t)b * NCOL + t * NDIM);
    const uint4 q0 = src[0];
    const uint4 q1 = src[1];
    __half2 mi[8];
    mi[0] = *reinterpret_cast<const __half2*>(&q0.x);
    mi[1] = *reinterpret_cast<const __half2*>(&q0.y);
    mi[2] = *reinterpret_cast<const __half2*>(&q0.z);
    mi[3] = *reinterpret_cast<const __half2*>(&q0.w);
    mi[4] = *reinterpret_cast<const __half2*>(&q1.x);
    mi[5] = *reinterpret_cast<const __half2*>(&q1.y);
    mi[6] = *reinterpret_cast<const __half2*>(&q1.z);
    mi[7] = *reinterpret_cast<const __half2*>(&q1.w);
#pragma unroll
    for (int q = 0; q < 8; q++) s2[q][t] = mi[q];
    s_acc[t] = 0.0f;
    __syncthreads();

    const __half hthr = __float2half(25.0f);
    float acc = 0.0f;

    auto do_pair = [&](int j) {
        __half2 d0 = __habs2(__hsub2(mi[0], s2[0][j]));
        __half2 d1 = __habs2(__hsub2(mi[1], s2[1][j]));
        __half2 d2 = __habs2(__hsub2(mi[2], s2[2][j]));
        __half2 d3 = __habs2(__hsub2(mi[3], s2[3][j]));
        __half2 d4 = __habs2(__hsub2(mi[4], s2[4][j]));
        __half2 d5 = __habs2(__hsub2(mi[5], s2[5][j]));
        __half2 d6 = __habs2(__hsub2(mi[6], s2[6][j]));
        __half2 d7 = __habs2(__hsub2(mi[7], s2[7][j]));
        __half2 s01 = __hadd2(d0, d1);
        __half2 s23 = __hadd2(d2, d3);
        __half2 s45 = __hadd2(d4, d5);
        __half2 s67 = __hadd2(d6, d7);
        __half2 s03 = __hadd2(s01, s23);
        __half2 s47 = __hadd2(s45, s67);
        __half2 n2  = __hadd2(s03, s47);
        __half  n   = __hadd(__low2half(n2), __high2half(n2));
        if (__hlt(n, hthr)) {
            float e = __expf(-__half2float(n));
            acc += e;                       // my row
            atomicAdd(&s_acc[j], e);        // partner row (rare)
        }
    };

#pragma unroll 4
    for (int r = 1; r < 64; r++)
        do_pair((t + r) & (NKERN - 1));
    if (t < 64)
        do_pair(t + 64);                    // offset-64 pairs, once each

    __syncthreads();
    out[b * NKERN + t] = 1.0f + acc + s_acc[t];
}

// ---------------------------------------------------------------------------
// Launcher (graph-capturable: kernel launches + attribute set)
// ---------------------------------------------------------------------------
extern "C" void kernel_launch(void* const* d_in, const int* in_sizes, int n_in,
                              void* d_out, int out_size) {
    const float* x = (const float*)d_in[0];   // [2048, 2048]
    const float* W = (const float*)d_in[1];   // [2048, 2048]
    float* out = (float*)d_out;               // [2048, 128]

    cudaFuncSetAttribute(gemm_kernel,
                         cudaFuncAttributeMaxDynamicSharedMemorySize, GEMM_SMEM);

    cvt_kernel<<<2048, 256>>>(x, W);

    dim3 grid(NCOL / BN, BATCH / BM);         // 16 x 16
    gemm_kernel<<<grid, 256, GEMM_SMEM>>>();

    pairwise_kernel<<<BATCH, 128>>>(out);
}